// round 2
// baseline (speedup 1.0000x reference)
#include <cuda_runtime.h>
#include <math.h>

#define B_  8
#define T_  4096
#define C_  64
#define F_  256
#define NL  8          // residual layers (dilations 2..256)
#define M_  (B_ * T_)  // 32768 rows

// Activation state buffers (static device globals — no runtime allocation).
__device__ float g_out [M_ * F_];  // residual stream [B*T, 256]
__device__ float g_skip[M_ * F_];  // skip accumulator
__device__ float g_z   [M_ * F_];  // gated activation per layer

__device__ __forceinline__ float sigmoidf_(float x) {
    return 1.0f / (1.0f + expf(-x));
}
__device__ __forceinline__ float seluf_(float x) {
    const float sc = 1.0507009873554804934193349852946f;
    const float al = 1.6732632423543772848170429916717f;
    return x > 0.0f ? sc * x : sc * al * (expf(x) - 1.0f);
}

// ---------------------------------------------------------------------------
// conv0: out[m,n] = x[b,t-1,:]·Wc[0,:,n] + x[b,t,:]·Wc[1,:,n]
// A[m,k]: k<64 -> x[b,t-1,k] (0 if t==0), else x[b,t,k-64].  B = Wc flat [128,256].
// Tile: BM=64, BN=64, Kb=16. 256 threads, 4x4 per thread.
// ---------------------------------------------------------------------------
__global__ void conv0_kernel(const float* __restrict__ x,
                             const float* __restrict__ Wc) {
    __shared__ float As[16][64];
    __shared__ float Bs[16][64];
    const int tid = threadIdx.x;
    const int tx = tid & 15, ty = tid >> 4;
    const int m0 = blockIdx.x * 64;
    const int n0 = blockIdx.y * 64;
    const int b  = m0 / T_;
    const int t0 = m0 % T_;

    float acc[4][4];
    #pragma unroll
    for (int i = 0; i < 4; ++i)
        #pragma unroll
        for (int j = 0; j < 4; ++j) acc[i][j] = 0.0f;

    const int lr  = tid >> 2;        // A-load row 0..63
    const int lk4 = (tid & 3) * 4;   // A-load k offset {0,4,8,12}

    for (int k0 = 0; k0 < 128; k0 += 16) {
        // A tile (transposed into smem)
        {
            const int t  = t0 + lr;
            const int kg = k0 + lk4;
            float4 av = make_float4(0.f, 0.f, 0.f, 0.f);
            if (kg < 64) {
                const int ts = t - 1;
                if (ts >= 0)
                    av = *(const float4*)&x[((size_t)b * T_ + ts) * C_ + kg];
            } else {
                av = *(const float4*)&x[((size_t)b * T_ + t) * C_ + (kg - 64)];
            }
            As[lk4 + 0][lr] = av.x; As[lk4 + 1][lr] = av.y;
            As[lk4 + 2][lr] = av.z; As[lk4 + 3][lr] = av.w;
        }
        // B tile
        {
            const int kk = tid >> 4;
            const int nn = (tid & 15) * 4;
            *(float4*)&Bs[kk][nn] =
                *(const float4*)&Wc[(size_t)(k0 + kk) * F_ + n0 + nn];
        }
        __syncthreads();
        #pragma unroll
        for (int k = 0; k < 16; ++k) {
            float4 a4 = *(float4*)&As[k][ty * 4];
            float4 b4 = *(float4*)&Bs[k][tx * 4];
            float aa[4] = {a4.x, a4.y, a4.z, a4.w};
            float bb[4] = {b4.x, b4.y, b4.z, b4.w};
            #pragma unroll
            for (int i = 0; i < 4; ++i)
                #pragma unroll
                for (int j = 0; j < 4; ++j) acc[i][j] += aa[i] * bb[j];
        }
        __syncthreads();
    }
    #pragma unroll
    for (int i = 0; i < 4; ++i) {
        const int m = m0 + ty * 4 + i;
        *(float4*)&g_out[(size_t)m * F_ + n0 + tx * 4] =
            make_float4(acc[i][0], acc[i][1], acc[i][2], acc[i][3]);
    }
}

// ---------------------------------------------------------------------------
// gated: z = tanh(A@Wf) * sigmoid(A@Wg)
// A[m,k]: k<256 -> out[b,t-d,k] (0 if t<d), else out[b,t,k-256].
// Wf/Wg are contiguous [512,256]. Dual-B: f and g share A tile loads.
// ---------------------------------------------------------------------------
__global__ void gated_kernel(const float* __restrict__ Wf,
                             const float* __restrict__ Wg, int d) {
    __shared__ float As [16][64];
    __shared__ float Bfs[16][64];
    __shared__ float Bgs[16][64];
    const int tid = threadIdx.x;
    const int tx = tid & 15, ty = tid >> 4;
    const int m0 = blockIdx.x * 64;
    const int n0 = blockIdx.y * 64;
    const int b  = m0 / T_;
    const int t0 = m0 % T_;

    float accf[4][4], accg[4][4];
    #pragma unroll
    for (int i = 0; i < 4; ++i)
        #pragma unroll
        for (int j = 0; j < 4; ++j) { accf[i][j] = 0.0f; accg[i][j] = 0.0f; }

    const int lr  = tid >> 2;
    const int lk4 = (tid & 3) * 4;

    for (int k0 = 0; k0 < 512; k0 += 16) {
        {
            const int t  = t0 + lr;
            const int kg = k0 + lk4;
            float4 av = make_float4(0.f, 0.f, 0.f, 0.f);
            if (kg < 256) {
                const int ts = t - d;
                if (ts >= 0)
                    av = *(const float4*)&g_out[((size_t)b * T_ + ts) * F_ + kg];
            } else {
                av = *(const float4*)&g_out[((size_t)b * T_ + t) * F_ + (kg - 256)];
            }
            As[lk4 + 0][lr] = av.x; As[lk4 + 1][lr] = av.y;
            As[lk4 + 2][lr] = av.z; As[lk4 + 3][lr] = av.w;
        }
        {
            const int kk = tid >> 4;
            const int nn = (tid & 15) * 4;
            const size_t boff = (size_t)(k0 + kk) * F_ + n0 + nn;
            *(float4*)&Bfs[kk][nn] = *(const float4*)&Wf[boff];
            *(float4*)&Bgs[kk][nn] = *(const float4*)&Wg[boff];
        }
        __syncthreads();
        #pragma unroll
        for (int k = 0; k < 16; ++k) {
            float4 a4 = *(float4*)&As [k][ty * 4];
            float4 f4 = *(float4*)&Bfs[k][tx * 4];
            float4 g4 = *(float4*)&Bgs[k][tx * 4];
            float aa[4] = {a4.x, a4.y, a4.z, a4.w};
            float ff[4] = {f4.x, f4.y, f4.z, f4.w};
            float gg[4] = {g4.x, g4.y, g4.z, g4.w};
            #pragma unroll
            for (int i = 0; i < 4; ++i)
                #pragma unroll
                for (int j = 0; j < 4; ++j) {
                    accf[i][j] += aa[i] * ff[j];
                    accg[i][j] += aa[i] * gg[j];
                }
        }
        __syncthreads();
    }
    #pragma unroll
    for (int i = 0; i < 4; ++i) {
        const int m = m0 + ty * 4 + i;
        float4 zv;
        zv.x = tanhf(accf[i][0]) * sigmoidf_(accg[i][0]);
        zv.y = tanhf(accf[i][1]) * sigmoidf_(accg[i][1]);
        zv.z = tanhf(accf[i][2]) * sigmoidf_(accg[i][2]);
        zv.w = tanhf(accf[i][3]) * sigmoidf_(accg[i][3]);
        *(float4*)&g_z[(size_t)m * F_ + n0 + tx * 4] = zv;
    }
}

// ---------------------------------------------------------------------------
// res_skip: out += z@Wr + br ; skip (= or +=) z@Ws + bs
// ---------------------------------------------------------------------------
__global__ void res_skip_kernel(const float* __restrict__ Wr,
                                const float* __restrict__ br,
                                const float* __restrict__ Ws,
                                const float* __restrict__ bs,
                                int first) {
    __shared__ float As [16][64];
    __shared__ float Brs[16][64];
    __shared__ float Bss[16][64];
    const int tid = threadIdx.x;
    const int tx = tid & 15, ty = tid >> 4;
    const int m0 = blockIdx.x * 64;
    const int n0 = blockIdx.y * 64;

    float accr[4][4], accs[4][4];
    #pragma unroll
    for (int i = 0; i < 4; ++i)
        #pragma unroll
        for (int j = 0; j < 4; ++j) { accr[i][j] = 0.0f; accs[i][j] = 0.0f; }

    const int lr  = tid >> 2;
    const int lk4 = (tid & 3) * 4;

    for (int k0 = 0; k0 < 256; k0 += 16) {
        {
            const int m  = m0 + lr;
            const int kg = k0 + lk4;
            float4 av = *(const float4*)&g_z[(size_t)m * F_ + kg];
            As[lk4 + 0][lr] = av.x; As[lk4 + 1][lr] = av.y;
            As[lk4 + 2][lr] = av.z; As[lk4 + 3][lr] = av.w;
        }
        {
            const int kk = tid >> 4;
            const int nn = (tid & 15) * 4;
            const size_t boff = (size_t)(k0 + kk) * F_ + n0 + nn;
            *(float4*)&Brs[kk][nn] = *(const float4*)&Wr[boff];
            *(float4*)&Bss[kk][nn] = *(const float4*)&Ws[boff];
        }
        __syncthreads();
        #pragma unroll
        for (int k = 0; k < 16; ++k) {
            float4 a4 = *(float4*)&As [k][ty * 4];
            float4 r4 = *(float4*)&Brs[k][tx * 4];
            float4 s4 = *(float4*)&Bss[k][tx * 4];
            float aa[4] = {a4.x, a4.y, a4.z, a4.w};
            float rr[4] = {r4.x, r4.y, r4.z, r4.w};
            float ss[4] = {s4.x, s4.y, s4.z, s4.w};
            #pragma unroll
            for (int i = 0; i < 4; ++i)
                #pragma unroll
                for (int j = 0; j < 4; ++j) {
                    accr[i][j] += aa[i] * rr[j];
                    accs[i][j] += aa[i] * ss[j];
                }
        }
        __syncthreads();
    }
    const float4 br4 = *(const float4*)&br[n0 + tx * 4];
    const float4 bs4 = *(const float4*)&bs[n0 + tx * 4];
    #pragma unroll
    for (int i = 0; i < 4; ++i) {
        const int m = m0 + ty * 4 + i;
        const size_t off = (size_t)m * F_ + n0 + tx * 4;
        float4 o = *(float4*)&g_out[off];
        o.x += accr[i][0] + br4.x; o.y += accr[i][1] + br4.y;
        o.z += accr[i][2] + br4.z; o.w += accr[i][3] + br4.w;
        *(float4*)&g_out[off] = o;

        float4 s;
        if (first) {
            s = make_float4(0.f, 0.f, 0.f, 0.f);
        } else {
            s = *(float4*)&g_skip[off];
        }
        s.x += accs[i][0] + bs4.x; s.y += accs[i][1] + bs4.y;
        s.z += accs[i][2] + bs4.z; s.w += accs[i][3] + bs4.w;
        *(float4*)&g_skip[off] = s;
    }
}

// ---------------------------------------------------------------------------
// head: y = selu(selu(skip)@Wd1 + bd1)@Wd2 + bd2
// 256 threads = 4 rows x 64 lanes per block.
// ---------------------------------------------------------------------------
__global__ void head_kernel(const float* __restrict__ Wd1,
                            const float* __restrict__ bd1,
                            const float* __restrict__ Wd2,
                            const float* __restrict__ bd2,
                            float* __restrict__ y) {
    __shared__ float hs [4][256];
    __shared__ float h2s[4][64];
    const int row  = threadIdx.x >> 6;   // 0..3
    const int lane = threadIdx.x & 63;   // 0..63
    const int m = blockIdx.x * 4 + row;

    for (int j = lane; j < 256; j += 64)
        hs[row][j] = seluf_(g_skip[(size_t)m * F_ + j]);
    __syncthreads();

    float acc = bd1[lane];
    #pragma unroll 8
    for (int k = 0; k < 256; ++k)
        acc += hs[row][k] * __ldg(&Wd1[(size_t)k * C_ + lane]);
    h2s[row][lane] = seluf_(acc);
    __syncthreads();

    float acc2 = bd2[lane];
    #pragma unroll 8
    for (int k = 0; k < 64; ++k)
        acc2 += h2s[row][k] * __ldg(&Wd2[(size_t)k * C_ + lane]);
    y[(size_t)m * C_ + lane] = acc2;
}

// ---------------------------------------------------------------------------
extern "C" void kernel_launch(void* const* d_in, const int* in_sizes, int n_in,
                              void* d_out, int out_size) {
    const float* x   = (const float*)d_in[0];
    const float* Wc  = (const float*)d_in[1];
    const float* Wf  = (const float*)d_in[2];
    const float* Wg  = (const float*)d_in[3];
    const float* Wr  = (const float*)d_in[4];
    const float* br  = (const float*)d_in[5];
    const float* Ws  = (const float*)d_in[6];
    const float* bs  = (const float*)d_in[7];
    const float* Wd1 = (const float*)d_in[8];
    const float* bd1 = (const float*)d_in[9];
    const float* Wd2 = (const float*)d_in[10];
    const float* bd2 = (const float*)d_in[11];
    float* y = (float*)d_out;

    dim3 blk(256);
    dim3 grid_g(M_ / 64, F_ / 64);  // 512 x 4

    conv0_kernel<<<grid_g, blk>>>(x, Wc);
    for (int i = 0; i < NL; ++i) {
        const int d = 2 << i;  // 2^(i+1): 2,4,...,256
        gated_kernel<<<grid_g, blk>>>(Wf + (size_t)i * 2 * F_ * F_,
                                      Wg + (size_t)i * 2 * F_ * F_, d);
        res_skip_kernel<<<grid_g, blk>>>(Wr + (size_t)i * F_ * F_,
                                         br + (size_t)i * F_,
                                         Ws + (size_t)i * F_ * F_,
                                         bs + (size_t)i * F_, i == 0);
    }
    head_kernel<<<M_ / 4, blk>>>(Wd1, bd1, Wd2, bd2, y);
}

// round 4
// speedup vs baseline: 1.4614x; 1.4614x over previous
#include <cuda_runtime.h>
#include <cuda_bf16.h>
#include <math.h>
#include <stdint.h>

#define B_  8
#define T_  4096
#define F_  256
#define NL  8
#define M_  (B_ * T_)
#define TILE_B 16384
#define SMEM_BYTES (1024 + 2 * 98304)

// tcgen05 only exists on arch-specific (sm_103a) compilation passes.
#if defined(__CUDA_ARCH_FEAT_SM103_ALL) || defined(__CUDA_ARCH_FEAT_SM100_ALL) || \
    defined(__CUDA_ARCH_FEAT_SM101_ALL) || defined(__CUDA_ARCH_SPECIFIC__) ||     \
    defined(__CUDA_ARCH_FAMILY_SPECIFIC__)
#define HAS_TCG 1
#else
#define HAS_TCG 0
#endif

__device__ float g_out [M_ * F_];
__device__ float g_skip[M_ * F_];
__device__ float g_z   [M_ * F_];
__device__ char  g_gB[(size_t)NL * 2 * 8 * 4 * TILE_B];
__device__ char  g_rB[(size_t)NL * 2 * 4 * 4 * TILE_B];
__device__ char  g_cB[(size_t)2 * 2 * 2 * TILE_B];

__host__ __device__ __forceinline__ uint32_t swz128(uint32_t x) { return x ^ ((x >> 3) & 0x70); }

__device__ __forceinline__ float sigmoidf_(float x) { return 1.0f / (1.0f + expf(-x)); }
__device__ __forceinline__ float seluf_(float x) {
    const float sc = 1.0507009873554804934193349852946f;
    const float al = 1.6732632423543772848170429916717f;
    return x > 0.0f ? sc * x : sc * al * (expf(x) - 1.0f);
}
__device__ __forceinline__ void split2(float v, __nv_bfloat16& h, __nv_bfloat16& l) {
    h = __float2bfloat16(v);
    l = __float2bfloat16(v - __bfloat162float(h));
}

#if HAS_TCG
// ---------------- tcgen05 helpers (arch-specific pass only) ----------------
__device__ __forceinline__ uint32_t elect_one_pred() {
    uint32_t p_;
    asm volatile("{\n\t.reg .pred p;\n\telect.sync _|p, 0xFFFFFFFF;\n\t"
                 "selp.b32 %0, 1, 0, p;\n\t}" : "=r"(p_));
    return p_;
}
__device__ __forceinline__ uint32_t smem_u32(const void* p) {
    uint32_t a;
    asm("{ .reg .u64 t; cvta.to.shared.u64 t, %1; cvt.u32.u64 %0, t; }" : "=r"(a) : "l"(p));
    return a;
}
#define MBARRIER_INIT(mb, c) \
    asm volatile("mbarrier.init.shared.b64 [%0], %1;" :: "r"((uint32_t)(mb)), "r"((uint32_t)(c)) : "memory")
#define MBARRIER_INVAL(mb) \
    asm volatile("mbarrier.inval.shared.b64 [%0];" :: "r"((uint32_t)(mb)) : "memory")
#define MBARRIER_WAIT_PARITY(mb, par) do {                                              \
    uint32_t _mb = (uint32_t)(mb), _pa = (uint32_t)(par), _done;                        \
    asm volatile("{\n\t.reg .pred p;\n\t"                                               \
        "mbarrier.try_wait.parity.acquire.cta.shared::cta.b64 p, [%1], %2;\n\t"         \
        "selp.b32 %0, 1, 0, p;\n\t}" : "=r"(_done) : "r"(_mb), "r"(_pa) : "memory");    \
    if (!_done) {                                                                       \
        asm volatile("{\n\t.reg .pred P1;\n\tWL_%=:\n\t"                                \
            "mbarrier.try_wait.parity.acquire.cta.shared::cta.b64 P1, [%0], %1, 0x989680;\n\t" \
            "@P1 bra.uni WD_%=;\n\tbra.uni WL_%=;\n\tWD_%=:\n\t}"                       \
            :: "r"(_mb), "r"(_pa) : "memory");                                          \
    } } while (0)

#define TCGEN05_ALLOC(sa, nc) \
    asm volatile("tcgen05.alloc.cta_group::1.sync.aligned.shared::cta.b32 [%0], %1;" \
                 :: "r"((uint32_t)(sa)), "r"((uint32_t)(nc)) : "memory")
#define TCGEN05_DEALLOC(tm, nc) \
    asm volatile("tcgen05.dealloc.cta_group::1.sync.aligned.b32 %0, %1;" :: "r"(tm), "r"((uint32_t)(nc)))
#define TCGEN05_COMMIT(mb) \
    asm volatile("tcgen05.commit.cta_group::1.mbarrier::arrive::one.shared::cluster.b64 [%0];" \
                 :: "r"((uint32_t)(mb)) : "memory")
#define TCGEN05_WAIT_LD()     asm volatile("tcgen05.wait::ld.sync.aligned;" ::: "memory")
#define TCGEN05_FENCE_AFTER() asm volatile("tcgen05.fence::after_thread_sync;" ::: "memory")
#define FENCE_PROXY_ASYNC()   asm volatile("fence.proxy.async.shared::cta;" ::: "memory")

#define TCGEN05_LD_X32(r, ta) \
    asm volatile("tcgen05.ld.sync.aligned.32x32b.x32.b32 " \
        "{%0,%1,%2,%3,%4,%5,%6,%7,%8,%9,%10,%11,%12,%13,%14,%15," \
        "%16,%17,%18,%19,%20,%21,%22,%23,%24,%25,%26,%27,%28,%29,%30,%31}, [%32];" \
        : "=r"((r)[0]),"=r"((r)[1]),"=r"((r)[2]),"=r"((r)[3]),"=r"((r)[4]),"=r"((r)[5]), \
          "=r"((r)[6]),"=r"((r)[7]),"=r"((r)[8]),"=r"((r)[9]),"=r"((r)[10]),"=r"((r)[11]), \
          "=r"((r)[12]),"=r"((r)[13]),"=r"((r)[14]),"=r"((r)[15]),"=r"((r)[16]),"=r"((r)[17]), \
          "=r"((r)[18]),"=r"((r)[19]),"=r"((r)[20]),"=r"((r)[21]),"=r"((r)[22]),"=r"((r)[23]), \
          "=r"((r)[24]),"=r"((r)[25]),"=r"((r)[26]),"=r"((r)[27]),"=r"((r)[28]),"=r"((r)[29]), \
          "=r"((r)[30]),"=r"((r)[31]) : "r"(ta))

static __device__ __forceinline__ uint64_t make_desc(uint32_t addr) {
    const uint64_t BASE = (uint64_t(2) << 61) | (uint64_t(1) << 46) |
                          (uint64_t(64) << 32) | (uint64_t(1) << 16);
    return BASE | ((uint64_t)(addr >> 4) & 0x3FFF);
}
#define IDESC_ ((1u << 4) | (1u << 7) | (1u << 10) | (16u << 17) | (8u << 24))

__device__ __forceinline__ void mma_f16(uint32_t d, uint64_t a, uint64_t b, uint32_t en) {
    asm volatile("{\n\t.reg .pred p;\n\tsetp.ne.u32 p, %3, 0;\n\t"
        "tcgen05.mma.cta_group::1.kind::f16 [%0], %1, %2, %4, {%5,%5,%5,%5}, p;\n\t}"
        :: "r"(d), "l"(a), "l"(b), "r"(en), "r"(IDESC_), "r"(0u) : "memory");
}
#endif  // HAS_TCG

// ---------------- weight preprocessing ----------------
__global__ __launch_bounds__(256) void prep_gated(const float* __restrict__ Wf,
                                                  const float* __restrict__ Wg) {
    uint32_t idx = blockIdx.x * 256u + threadIdx.x;
    int n = idx & 255, k = (idx >> 8) & 511, i = idx >> 17;
    uint32_t off = swz128((uint32_t)(n & 127) * 128u + (uint32_t)(k & 63) * 2u);
    char* base = g_gB + ((((size_t)i * 2 + (n >> 7)) * 8 + (k >> 6)) * 4) * TILE_B;
    __nv_bfloat16 h, l;
    split2(Wf[idx], h, l);
    *(__nv_bfloat16*)(base + 0 * TILE_B + off) = h;
    *(__nv_bfloat16*)(base + 1 * TILE_B + off) = l;
    split2(Wg[idx], h, l);
    *(__nv_bfloat16*)(base + 2 * TILE_B + off) = h;
    *(__nv_bfloat16*)(base + 3 * TILE_B + off) = l;
}
__global__ __launch_bounds__(256) void prep_res(const float* __restrict__ Wr,
                                                const float* __restrict__ Ws) {
    uint32_t idx = blockIdx.x * 256u + threadIdx.x;
    int n = idx & 255, k = (idx >> 8) & 255, i = idx >> 16;
    uint32_t off = swz128((uint32_t)(n & 127) * 128u + (uint32_t)(k & 63) * 2u);
    char* base = g_rB + ((((size_t)i * 2 + (n >> 7)) * 4 + (k >> 6)) * 4) * TILE_B;
    __nv_bfloat16 h, l;
    split2(Wr[idx], h, l);
    *(__nv_bfloat16*)(base + 0 * TILE_B + off) = h;
    *(__nv_bfloat16*)(base + 1 * TILE_B + off) = l;
    split2(Ws[idx], h, l);
    *(__nv_bfloat16*)(base + 2 * TILE_B + off) = h;
    *(__nv_bfloat16*)(base + 3 * TILE_B + off) = l;
}
__global__ __launch_bounds__(256) void prep_conv(const float* __restrict__ Wc) {
    uint32_t idx = blockIdx.x * 256u + threadIdx.x;
    int n = idx & 255, k = idx >> 8;
    uint32_t off = swz128((uint32_t)(n & 127) * 128u + (uint32_t)(k & 63) * 2u);
    char* base = g_cB + (((size_t)(n >> 7) * 2 + (k >> 6)) * 2) * TILE_B;
    __nv_bfloat16 h, l;
    split2(Wc[idx], h, l);
    *(__nv_bfloat16*)(base + 0 * TILE_B + off) = h;
    *(__nv_bfloat16*)(base + 1 * TILE_B + off) = l;
}

// A-tile fill: fp32 gather (dilated causal) -> bf16 hi/lo, SW128 swizzled.
__device__ __forceinline__ void fill_A(char* Ah, char* Al, const float* Asrc,
                                       int astride, int b, int t0, int fr, int cg,
                                       int c, int shift_chunks, int dil) {
    const int tsh  = (c < shift_chunks) ? dil : 0;
    const int kcol = (c < shift_chunks) ? c * 64 : (c - shift_chunks) * 64;
    const int t = t0 + fr - tsh;
    const bool valid = (t0 + fr) >= tsh;
    const float* src = Asrc + ((size_t)(b * T_ + t)) * astride + kcol + cg;
    #pragma unroll
    for (int j = 0; j < 8; ++j) {
        float4 v = valid ? *(const float4*)(src + j * 4) : make_float4(0.f, 0.f, 0.f, 0.f);
        uint32_t off = swz128((uint32_t)fr * 128u + (uint32_t)(cg + j * 4) * 2u);
        __nv_bfloat16 h0, l0, h1, l1, h2, l2, h3, l3;
        split2(v.x, h0, l0); split2(v.y, h1, l1);
        split2(v.z, h2, l2); split2(v.w, h3, l3);
        uint2 hh, ll;
        hh.x = (uint32_t)__bfloat16_as_ushort(h0) | ((uint32_t)__bfloat16_as_ushort(h1) << 16);
        hh.y = (uint32_t)__bfloat16_as_ushort(h2) | ((uint32_t)__bfloat16_as_ushort(h3) << 16);
        ll.x = (uint32_t)__bfloat16_as_ushort(l0) | ((uint32_t)__bfloat16_as_ushort(l1) << 16);
        ll.y = (uint32_t)__bfloat16_as_ushort(l2) | ((uint32_t)__bfloat16_as_ushort(l3) << 16);
        *(uint2*)(Ah + off) = hh;
        *(uint2*)(Al + off) = ll;
    }
}

__device__ __forceinline__ float2 dec2(const char* hp, const char* lp, uint32_t off) {
    __nv_bfloat162 h = *(const __nv_bfloat162*)(hp + off);
    __nv_bfloat162 l = *(const __nv_bfloat162*)(lp + off);
    float2 fh = __bfloat1622float2(h), fl = __bfloat1622float2(l);
    return make_float2(fh.x + fl.x, fh.y + fl.y);
}

// ---------------- unified GEMM layer ----------------
// mode 0: conv0 (1 mat -> g_out), 1: gated (f,g -> g_z), 2: res/skip (RMW)
__global__ __launch_bounds__(256, 1) void mma_layer(
    const float* __restrict__ Asrc, const char* __restrict__ Bbase,
    const float* __restrict__ br, const float* __restrict__ bs,
    int astride, int n_chunks, int n_mats, int shift_chunks, int dil,
    int mode, int first)
{
    extern __shared__ char smem[];
    const int tid = threadIdx.x;
    const int m0 = blockIdx.x * 128;
    const int n0 = blockIdx.y * 128;
    const int b  = m0 / T_;
    const int t0 = m0 % T_;
    const int n_tiles = n_mats * 2;
    const int fr = tid >> 1;
    const int cg = (tid & 1) * 32;

#if HAS_TCG
    const uint32_t sbase = smem_u32(smem);
    const int wid = tid >> 5;
    const uint32_t mbar0 = sbase;
    const uint32_t tptr  = sbase + 16;

    if (tid == 0) { MBARRIER_INIT(mbar0, 1); MBARRIER_INIT(mbar0 + 8, 1); }
    if (wid == 0) TCGEN05_ALLOC(tptr, 256);
    __syncthreads();
    uint32_t tmem;
    asm volatile("ld.shared.b32 %0, [%1];" : "=r"(tmem) : "r"(tptr));

    for (int c = 0; c < n_chunks; ++c) {
        const int buf = c & 1;
        const uint32_t abase = sbase + 1024 + buf * 98304;
        const uint32_t bbase = abase + 32768;
        char* Ah = smem + 1024 + buf * 98304;
        char* Al = Ah + TILE_B;
        char* Bt = Al + TILE_B;

        if (c >= 2) MBARRIER_WAIT_PARITY(mbar0 + 8 * buf, ((c - 2) >> 1) & 1);

        fill_A(Ah, Al, Asrc, astride, b, t0, fr, cg, c, shift_chunks, dil);
        {
            const uint4* src = (const uint4*)(Bbase +
                ((size_t)(blockIdx.y * n_chunks + c) * n_tiles) * TILE_B);
            uint4* dst = (uint4*)Bt;
            const int cnt = n_tiles * 1024;
            for (int j = tid; j < cnt; j += 256) dst[j] = src[j];
        }
        FENCE_PROXY_ASYNC();
        __syncthreads();

        if (wid == 0) {
            if (elect_one_pred()) {
                const uint64_t ah = make_desc(abase);
                const uint64_t al = ah + (TILE_B >> 4);
                for (int mat = 0; mat < n_mats; ++mat) {
                    const uint64_t bh = make_desc(bbase + (uint32_t)(mat * 2) * TILE_B);
                    const uint64_t bl = bh + (TILE_B >> 4);
                    const uint32_t dD = tmem + mat * 128;
                    #pragma unroll
                    for (int ks = 0; ks < 4; ++ks)
                        mma_f16(dD, ah + ks * 2, bh + ks * 2, !(c == 0 && ks == 0));
                    #pragma unroll
                    for (int ks = 0; ks < 4; ++ks)
                        mma_f16(dD, ah + ks * 2, bl + ks * 2, 1u);
                    #pragma unroll
                    for (int ks = 0; ks < 4; ++ks)
                        mma_f16(dD, al + ks * 2, bh + ks * 2, 1u);
                }
                TCGEN05_COMMIT(mbar0 + 8 * buf);
            }
        }
    }

    MBARRIER_WAIT_PARITY(mbar0 + 8 * ((n_chunks - 1) & 1), ((n_chunks >> 1) - 1) & 1);
    TCGEN05_FENCE_AFTER();

    if (wid < 4) {
        const int lane = tid & 31;
        const int m = m0 + wid * 32 + lane;
        #pragma unroll
        for (int cb = 0; cb < 4; ++cb) {
            uint32_t rf[32], rg[32];
            TCGEN05_LD_X32(rf, tmem + cb * 32);
            if (n_mats == 2) TCGEN05_LD_X32(rg, tmem + 128 + cb * 32);
            TCGEN05_WAIT_LD();
            const int nc = n0 + cb * 32;
            if (mode == 1) {
                #pragma unroll
                for (int j = 0; j < 32; ++j)
                    g_z[(size_t)m * F_ + nc + j] =
                        tanhf(__uint_as_float(rf[j])) * sigmoidf_(__uint_as_float(rg[j]));
            } else if (mode == 0) {
                #pragma unroll
                for (int j = 0; j < 32; ++j)
                    g_out[(size_t)m * F_ + nc + j] = __uint_as_float(rf[j]);
            } else {
                #pragma unroll
                for (int j = 0; j < 32; ++j) {
                    const size_t off = (size_t)m * F_ + nc + j;
                    g_out[off] += __uint_as_float(rf[j]) + __ldg(&br[nc + j]);
                    const float sp = first ? 0.0f : g_skip[off];
                    g_skip[off] = sp + __uint_as_float(rg[j]) + __ldg(&bs[nc + j]);
                }
            }
        }
    }
    __syncthreads();
    if (tid == 0) { MBARRIER_INVAL(mbar0); MBARRIER_INVAL(mbar0 + 8); }
    if (wid == 0) TCGEN05_DEALLOC(tmem, 256);
#else
    // -------- generic-arch fallback: SIMT FFMA on the same data layout --------
    char* Ah = smem;
    char* Al = smem + TILE_B;
    char* Bt = smem + 2 * TILE_B;   // single mat hi/lo: 2*TILE_B
    const int ty = tid >> 4, tx = tid & 15;

    for (int mat = 0; mat < n_mats; ++mat) {
        float acc[8][8];
        #pragma unroll
        for (int i = 0; i < 8; ++i)
            #pragma unroll
            for (int j = 0; j < 8; ++j) acc[i][j] = 0.0f;

        for (int c = 0; c < n_chunks; ++c) {
            __syncthreads();
            fill_A(Ah, Al, Asrc, astride, b, t0, fr, cg, c, shift_chunks, dil);
            {
                const uint4* src = (const uint4*)(Bbase +
                    ((size_t)(blockIdx.y * n_chunks + c) * n_tiles + mat * 2) * TILE_B);
                uint4* dst = (uint4*)Bt;
                for (int j = tid; j < 2048; j += 256) dst[j] = src[j];
            }
            __syncthreads();
            #pragma unroll 4
            for (int k2 = 0; k2 < 32; ++k2) {
                float2 a2[8], b2[8];
                #pragma unroll
                for (int i = 0; i < 8; ++i)
                    a2[i] = dec2(Ah, Al, swz128((uint32_t)(ty * 8 + i) * 128u + k2 * 4u));
                #pragma unroll
                for (int j = 0; j < 8; ++j)
                    b2[j] = dec2(Bt, Bt + TILE_B, swz128((uint32_t)(tx * 8 + j) * 128u + k2 * 4u));
                #pragma unroll
                for (int i = 0; i < 8; ++i)
                    #pragma unroll
                    for (int j = 0; j < 8; ++j)
                        acc[i][j] += a2[i].x * b2[j].x + a2[i].y * b2[j].y;
            }
        }
        // epilogue per mat
        #pragma unroll
        for (int i = 0; i < 8; ++i) {
            const int m = m0 + ty * 8 + i;
            #pragma unroll
            for (int j = 0; j < 8; ++j) {
                const int n = n0 + tx * 8 + j;
                const size_t off = (size_t)m * F_ + n;
                if (mode == 0) {
                    g_out[off] = acc[i][j];
                } else if (mode == 1) {
                    if (mat == 0) g_z[off] = acc[i][j];  // stash raw f
                    else g_z[off] = tanhf(g_z[off]) * sigmoidf_(acc[i][j]);
                } else {
                    if (mat == 0) {
                        g_out[off] += acc[i][j] + br[n];
                    } else {
                        const float sp = first ? 0.0f : g_skip[off];
                        g_skip[off] = sp + acc[i][j] + bs[n];
                    }
                }
            }
        }
    }
#endif
}

// ---------------- head ----------------
__global__ void head_kernel(const float* __restrict__ Wd1, const float* __restrict__ bd1,
                            const float* __restrict__ Wd2, const float* __restrict__ bd2,
                            float* __restrict__ y) {
    __shared__ float hs[4][256];
    __shared__ float h2s[4][64];
    const int row = threadIdx.x >> 6, lane = threadIdx.x & 63;
    const int m = blockIdx.x * 4 + row;
    for (int j = lane; j < 256; j += 64) hs[row][j] = seluf_(g_skip[(size_t)m * F_ + j]);
    __syncthreads();
    float acc = bd1[lane];
    #pragma unroll 8
    for (int k = 0; k < 256; ++k) acc += hs[row][k] * __ldg(&Wd1[(size_t)k * 64 + lane]);
    h2s[row][lane] = seluf_(acc);
    __syncthreads();
    float acc2 = bd2[lane];
    #pragma unroll 8
    for (int k = 0; k < 64; ++k) acc2 += h2s[row][k] * __ldg(&Wd2[(size_t)k * 64 + lane]);
    y[(size_t)m * 64 + lane] = acc2;
}

// ---------------------------------------------------------------------------
extern "C" void kernel_launch(void* const* d_in, const int* in_sizes, int n_in,
                              void* d_out, int out_size) {
    const float* x   = (const float*)d_in[0];
    const float* Wc  = (const float*)d_in[1];
    const float* Wf  = (const float*)d_in[2];
    const float* Wg  = (const float*)d_in[3];
    const float* Wr  = (const float*)d_in[4];
    const float* br  = (const float*)d_in[5];
    const float* Ws  = (const float*)d_in[6];
    const float* bs  = (const float*)d_in[7];
    const float* Wd1 = (const float*)d_in[8];
    const float* bd1 = (const float*)d_in[9];
    const float* Wd2 = (const float*)d_in[10];
    const float* bd2 = (const float*)d_in[11];
    float* y = (float*)d_out;

    cudaFuncSetAttribute(mma_layer, cudaFuncAttributeMaxDynamicSharedMemorySize, SMEM_BYTES);

    char* gB; cudaGetSymbolAddress((void**)&gB, g_gB);
    char* rB; cudaGetSymbolAddress((void**)&rB, g_rB);
    char* cB; cudaGetSymbolAddress((void**)&cB, g_cB);
    float* outp; cudaGetSymbolAddress((void**)&outp, g_out);
    float* zp;   cudaGetSymbolAddress((void**)&zp, g_z);

    prep_gated<<<4096, 256>>>(Wf, Wg);
    prep_res  <<<2048, 256>>>(Wr, Ws);
    prep_conv <<<128,  256>>>(Wc);

    dim3 grid(M_ / 128, 2), blk(256);
    mma_layer<<<grid, blk, SMEM_BYTES>>>(x, cB, nullptr, nullptr,
                                         64, 2, 1, 1, 1, 0, 0);
    for (int i = 0; i < NL; ++i) {
        const int d = 2 << i;
        mma_layer<<<grid, blk, SMEM_BYTES>>>(
            outp, gB + (size_t)i * 2 * 8 * 4 * TILE_B, nullptr, nullptr,
            256, 8, 2, 4, d, 1, 0);
        mma_layer<<<grid, blk, SMEM_BYTES>>>(
            zp, rB + (size_t)i * 2 * 4 * 4 * TILE_B,
            br + (size_t)i * F_, bs + (size_t)i * F_,
            256, 4, 2, 0, 0, 2, i == 0);
    }
    head_kernel<<<M_ / 4, 256>>>(Wd1, bd1, Wd2, bd2, y);
}